// round 10
// baseline (speedup 1.0000x reference)
#include <cuda_runtime.h>
#include <math.h>

#define BB 2
#define CC 128
#define HH 48
#define WW 48
#define PP (HH*WW)      // 2304
#define BPP (BB*PP)     // 4608
#define HD 24
#define WIN 13
#define KK2 169
#define NG 32
#define NT 72

typedef unsigned long long ull;

// ---------------- scratch (static device globals; no allocation) ----------------
__device__ float g_xt[BB*PP*CC];         // x transposed, pixel-major [b,p,c]
__device__ float g_xn[BB*PP*CC];         // normalized x, pixel-major [pix][c]
__device__ float4 g_xn4[32*BPP];         // normalized x, group-major [cg][pix]
__device__ float g_m[BPP];
__device__ float g_df[BPP];
__device__ int   g_dmin[BB];
__device__ int   g_dmax[BB];
__device__ float g_gps[BB*NG*NT];
__device__ float g_gpq[BB*NG*NT];
__device__ float g_mu[BB*NG];
__device__ float g_rstd[BB*NG];
__device__ float g_enh[BB*PP*CC];

__device__ __forceinline__ void fma2(ull& d, ull a, ull b, ull c) {
    asm("fma.rn.f32x2 %0, %1, %2, %3;" : "=l"(d) : "l"(a), "l"(b), "l"(c));
}
__device__ __forceinline__ void add2(ull& d, ull a, ull b) {
    asm("add.rn.f32x2 %0, %1, %2;" : "=l"(d) : "l"(a), "l"(b));
}
__device__ __forceinline__ ull dup2(float v) {
    ull r; unsigned u = __float_as_uint(v);
    asm("mov.b64 %0, {%1, %1};" : "=l"(r) : "r"(u));
    return r;
}
__device__ __forceinline__ ull pack2(float a, float b) {
    ull r; asm("mov.b64 %0, {%1, %2};" : "=l"(r) : "r"(__float_as_uint(a)), "r"(__float_as_uint(b)));
    return r;
}
__device__ __forceinline__ float lo2(ull v) { return __uint_as_float((unsigned)(v & 0xffffffffull)); }
__device__ __forceinline__ float hi2(ull v) { return __uint_as_float((unsigned)(v >> 32)); }
__device__ __forceinline__ int refl(int v, int n) {
    return v < 0 ? -v : (v >= n ? 2 * n - 2 - v : v);
}
// jax bilinear 24->48 weights (edge-renormalized triangle)
__device__ __forceinline__ void upw(int o, int& i0, float& w0, int& i1, float& w1v) {
    if (o & 1) { i0 = (o - 1) >> 1; i1 = i0 + 1; w0 = 0.75f; w1v = 0.25f;
                 if (i1 >= HD) { i1 = i0; w0 = 1.0f; w1v = 0.0f; } }
    else       { i1 = o >> 1; i0 = i1 - 1; w1v = 0.75f; w0 = 0.25f;
                 if (i0 < 0) { i0 = i1; w0 = 0.0f; w1v = 1.0f; } }
}

// ---------------- k_t: NCHW -> pixel-major transpose + GN partial sums + init ----------------
__global__ void __launch_bounds__(256) k_t(const float* __restrict__ x) {
    __shared__ float tile[32][33];
    __shared__ float sS[8][4], sQ[8][4];
    int tx = threadIdx.x & 31, ty = threadIdx.x >> 5;
    int tb = blockIdx.x, cb = blockIdx.y, b = blockIdx.z;
    if (tb == 0 && cb == 0 && b == 0 && threadIdx.x < BB) {
        g_dmin[threadIdx.x] = 0x7f7fffff; g_dmax[threadIdx.x] = 0;
    }
    int c0 = cb * 32, p0 = tb * 32;
    #pragma unroll
    for (int k = 0; k < 4; k++) {
        int c = c0 + ty + 8 * k;
        float v = x[(b * CC + c) * PP + p0 + tx];
        tile[ty + 8 * k][tx] = v;
        float s = v, q = v * v;
        #pragma unroll
        for (int off = 16; off; off >>= 1) {
            s += __shfl_xor_sync(~0u, s, off);
            q += __shfl_xor_sync(~0u, q, off);
        }
        if (tx == 0) { sS[ty][k] = s; sQ[ty][k] = q; }
    }
    __syncthreads();
    #pragma unroll
    for (int k = 0; k < 4; k++) {
        int p = p0 + ty + 8 * k;
        g_xt[(b * PP + p) * CC + c0 + tx] = tile[tx][ty + 8 * k];
    }
    if (threadIdx.x < 8) {
        int k = threadIdx.x >> 1, m = threadIdx.x & 1;
        float s = sS[4*m][k] + sS[4*m+1][k] + sS[4*m+2][k] + sS[4*m+3][k];
        float q = sQ[4*m][k] + sQ[4*m+1][k] + sQ[4*m+2][k] + sQ[4*m+3][k];
        int g = 8 * cb + threadIdx.x;
        g_gps[(b * NG + g) * NT + tb] = s;
        g_gpq[(b * NG + g) * NT + tb] = q;
    }
}

// ---------------- k_pix: warp/pixel; inline 2x2-mean taps, df, norm, both xn layouts, GN finalize ----------------
__global__ void __launch_bounds__(256) k_pix() {
    // GN finalize in first 64 blocks (g_gps written by k_t, previous launch)
    if (blockIdx.x < BB * NG) {
        __shared__ float fs[NT], fq[NT];
        int bg = blockIdx.x;
        if (threadIdx.x < NT) {
            fs[threadIdx.x] = g_gps[bg * NT + threadIdx.x];
            fq[threadIdx.x] = g_gpq[bg * NT + threadIdx.x];
        }
        __syncthreads();
        if (threadIdx.x == 0) {
            float s = 0.f, q = 0.f;
            for (int i = 0; i < NT; i++) { s += fs[i]; q += fq[i]; }
            const float invn = 1.0f / (4.0f * PP);
            float mu = s * invn;
            float var = q * invn - mu * mu;
            g_mu[bg] = mu;
            g_rstd[bg] = rsqrtf(var + 1e-5f);
        }
    }

    int warp = threadIdx.x >> 5, lane = threadIdx.x & 31;
    int pix = blockIdx.x * 8 + warp;              // 576*8 = 4608
    int b = pix / PP, p = pix - b * PP;
    int h = p / WW, w = p - h * WW;
    const float4 v4 = *(const float4*)(g_xt + pix * CC + 4 * lane);

    int r0, r1, c0, c1; float wr0, wr1, wc0, wc1;
    upw(h, r0, wr0, r1, wr1);
    upw(w, c0, wc0, c1, wc1);

    const float* xb = g_xt + b * PP * CC + 4 * lane;
    float4 dv[2][2];
    #pragma unroll
    for (int rr = 0; rr < 2; rr++) {
        int r = rr ? r1 : r0;
        #pragma unroll
        for (int cc2 = 0; cc2 < 2; cc2++) {
            int c = cc2 ? c1 : c0;
            const float* bp = xb + ((2 * r) * WW + 2 * c) * CC;
            float4 a0 = *(const float4*)(bp);
            float4 a1 = *(const float4*)(bp + CC);
            float4 a2 = *(const float4*)(bp + WW * CC);
            float4 a3 = *(const float4*)(bp + WW * CC + CC);
            dv[rr][cc2].x = 0.25f * (a0.x + a1.x + a2.x + a3.x);
            dv[rr][cc2].y = 0.25f * (a0.y + a1.y + a2.y + a3.y);
            dv[rr][cc2].z = 0.25f * (a0.z + a1.z + a2.z + a3.z);
            dv[rr][cc2].w = 0.25f * (a0.w + a1.w + a2.w + a3.w);
        }
    }
    float x0 = wr0 * (wc0 * dv[0][0].x + wc1 * dv[0][1].x) + wr1 * (wc0 * dv[1][0].x + wc1 * dv[1][1].x);
    float x1 = wr0 * (wc0 * dv[0][0].y + wc1 * dv[0][1].y) + wr1 * (wc0 * dv[1][0].y + wc1 * dv[1][1].y);
    float x2 = wr0 * (wc0 * dv[0][0].z + wc1 * dv[0][1].z) + wr1 * (wc0 * dv[1][0].z + wc1 * dv[1][1].z);
    float x3 = wr0 * (wc0 * dv[0][0].w + wc1 * dv[0][1].w) + wr1 * (wc0 * dv[1][0].w + wc1 * dv[1][1].w);

    float a = fabsf(v4.x - x0) + fabsf(v4.y - x1) + fabsf(v4.z - x2) + fabsf(v4.w - x3);
    float q = v4.x * v4.x + v4.y * v4.y + v4.z * v4.z + v4.w * v4.w;
    #pragma unroll
    for (int off = 16; off; off >>= 1) {
        a += __shfl_xor_sync(~0u, a, off);
        q += __shfl_xor_sync(~0u, q, off);
    }
    float m = fmaxf(sqrtf(q), 1e-12f);
    if (lane == 0) {
        g_df[pix] = a;
        atomicMin(&g_dmin[b], __float_as_int(a));
        atomicMax(&g_dmax[b], __float_as_int(a));
        g_m[pix] = m;
    }
    float inv = 1.0f / m;
    float4 o; o.x = v4.x * inv; o.y = v4.y * inv; o.z = v4.z * inv; o.w = v4.w * inv;
    *(float4*)(g_xn + pix * CC + 4 * lane) = o;   // pixel-major (gather/xp)
    g_xn4[lane * BPP + pix] = o;                  // group-major  (sims)
}

// ---------------- k_main: lane-owns-neighbor sims + stable top-k + gather + GN fuse ----------------
__global__ void __launch_bounds__(256) k_main(const float* __restrict__ gamma,
                                              const float* __restrict__ beta) {
    __shared__ float4 sXP[8][32];
    int warp = threadIdx.x >> 5, lane = threadIdx.x & 31;
    int pix = blockIdx.x * 8 + warp;
    int b = pix / PP, p = pix - b * PP;
    int h = p / WW, w = p - h * WW;
    const float* xnb = g_xn + b * PP * CC;
    const float4 xp4 = *(const float4*)(xnb + p * CC + 4 * lane);
    sXP[warp][lane] = xp4;
    __syncwarp();

    float df = g_df[pix];
    float dmin = __int_as_float(g_dmin[b]);
    float dmax = __int_as_float(g_dmax[b]);
    float dn = (df - dmin) / (dmax - dmin + 1e-8f);
    int kcnt = (int)(1.0f + rintf(dn * 15.0f));   // round-half-even == jnp.round
    if (kcnt < 1) kcnt = 1;
    if (kcnt > 16) kcnt = 16;

    // lane owns neighbors kk = 32t + lane (t = 0..5)
    int qg[6];
    float acc[6];
    #pragma unroll
    for (int t = 0; t < 6; t++) {
        int kk = 32 * t + lane;
        if (kk > KK2 - 1) kk = KK2 - 1;           // addr clamp; value masked later
        int ii = (kk * 79) >> 10;                 // exact kk/13 for kk<169
        int jj = kk - 13 * ii;
        int r  = refl(h + ii - 6, HH);
        int cq = refl(w + jj - 6, WW);
        qg[t] = b * PP + r * WW + cq;
        acc[t] = 0.f;
    }
    const float4* xn4 = g_xn4;
    #pragma unroll 4
    for (int cg = 0; cg < 32; cg++) {
        const float4 xpv = sXP[warp][cg];
        const float4* row = xn4 + cg * BPP;
        #pragma unroll
        for (int t = 0; t < 6; t++) {
            float4 qv = row[qg[t]];
            acc[t] += xpv.x * qv.x + xpv.y * qv.y + xpv.z * qv.z + xpv.w * qv.w;
        }
    }
    if (lane >= 9) acc[5] = -1e30f;               // kk = 160+lane >= 169

    // ---- iterative top-k: max value, tie -> smallest index (stable argsort mask) ----
    unsigned taken = 0;
    int selk[16]; float selw[16];
    float sumexp = 0.f;
    #pragma unroll
    for (int it = 0; it < 16; it++) {
        if (it < kcnt) {                          // kcnt warp-uniform
            float bv = -1e30f; int bt = 0;
            #pragma unroll
            for (int t = 0; t < 6; t++) {
                float cand = (taken & (1u << t)) ? -1e30f : acc[t];
                if (cand > bv) { bv = cand; bt = t; }
            }
            int bk = lane + 32 * bt;
            #pragma unroll
            for (int off = 16; off; off >>= 1) {
                float ov = __shfl_xor_sync(~0u, bv, off);
                int   ok = __shfl_xor_sync(~0u, bk, off);
                if (ov > bv || (ov == bv && ok < bk)) { bv = ov; bk = ok; }
            }
            if (lane == (bk & 31)) taken |= (1u << (bk >> 5));
            float e = __expf(bv);
            selk[it] = bk; selw[it] = e; sumexp += e;
        }
    }

    // ---- weighted aggregation: out = sum w_k * (xn_q * m_q), coalesced pixel-major reads ----
    float inv = 1.0f / sumexp;
    float4 out4 = make_float4(0.f, 0.f, 0.f, 0.f);
    #pragma unroll
    for (int it = 0; it < 16; it++) {
        if (it < kcnt) {
            int kk = selk[it];
            int ii = (kk * 79) >> 10;
            int jj = kk - 13 * ii;
            int r  = refl(h + ii - 6, HH);
            int cq = refl(w + jj - 6, WW);
            int q = r * WW + cq;
            float wgt = selw[it] * inv * g_m[b * PP + q];
            const float4 vq = *(const float4*)(xnb + q * CC + 4 * lane);
            out4.x += wgt * vq.x; out4.y += wgt * vq.y;
            out4.z += wgt * vq.z; out4.w += wgt * vq.w;
        }
    }

    // ---- GroupNorm fuse: group == lane (c = 4*lane..4*lane+3) ----
    float mp = g_m[pix];
    float mu = g_mu[b * NG + lane];
    float rs = g_rstd[b * NG + lane];
    float4 gm  = *(const float4*)(gamma + 4 * lane);
    float4 bt4 = *(const float4*)(beta + 4 * lane);
    float4 e4;
    e4.x = out4.x + (xp4.x * mp - mu) * rs * gm.x + bt4.x;
    e4.y = out4.y + (xp4.y * mp - mu) * rs * gm.y + bt4.y;
    e4.z = out4.z + (xp4.z * mp - mu) * rs * gm.z + bt4.z;
    e4.w = out4.w + (xp4.w * mp - mu) * rs * gm.w + bt4.w;
    *(float4*)(g_enh + pix * CC + 4 * lane) = e4;
}

// ---------------- k_ffn: register-tiled GEMM pair, f32x2, 48KB smem ----------------
__global__ void __launch_bounds__(256) k_ffn(const float* __restrict__ w1,
                                             const float* __restrict__ b1,
                                             const float* __restrict__ w2,
                                             const float* __restrict__ b2,
                                             float* __restrict__ out) {
    __shared__ __align__(16) ull sE_u[128 * 16];
    __shared__ __align__(16) ull sH_u[256 * 16];
    float* sE_f = (float*)sE_u;
    int tid = threadIdx.x;
    int pix0 = blockIdx.x * 32;
    int b = pix0 / PP;

    {
        const float4* eg = (const float4*)(g_enh + pix0 * CC);
        #pragma unroll
        for (int i = 0; i < 4; i++) {
            int idx = tid + 256 * i;
            int p = idx >> 5, c4 = idx & 31;
            float4 v = eg[idx];
            sE_f[(4 * c4 + 0) * 32 + p] = v.x;
            sE_f[(4 * c4 + 1) * 32 + p] = v.y;
            sE_f[(4 * c4 + 2) * 32 + p] = v.z;
            sE_f[(4 * c4 + 3) * 32 + p] = v.w;
        }
    }
    __syncthreads();

    int pi = tid & 3;
    int ni = tid >> 2;

    {   // GEMM1
        ull acc[4][4];
        #pragma unroll
        for (int m = 0; m < 4; m++)
            #pragma unroll
            for (int j = 0; j < 4; j++) acc[m][j] = 0ull;
        const float4* w1v4 = (const float4*)w1;
        #pragma unroll 2
        for (int kt = 0; kt < 32; kt++) {
            float4 wv[4];
            #pragma unroll
            for (int m = 0; m < 4; m++) wv[m] = w1v4[(ni * 4 + m) * 32 + kt];
            ulonglong2 e2[4][2];
            #pragma unroll
            for (int kk = 0; kk < 4; kk++) {
                const ulonglong2* ep = (const ulonglong2*)(sE_u + (4 * kt + kk) * 16 + pi * 4);
                e2[kk][0] = ep[0]; e2[kk][1] = ep[1];
            }
            #pragma unroll
            for (int kk = 0; kk < 4; kk++) {
                #pragma unroll
                for (int m = 0; m < 4; m++) {
                    float wf = (kk == 0) ? wv[m].x : (kk == 1) ? wv[m].y : (kk == 2) ? wv[m].z : wv[m].w;
                    ull wd = dup2(wf);
                    fma2(acc[m][0], e2[kk][0].x, wd, acc[m][0]);
                    fma2(acc[m][1], e2[kk][0].y, wd, acc[m][1]);
                    fma2(acc[m][2], e2[kk][1].x, wd, acc[m][2]);
                    fma2(acc[m][3], e2[kk][1].y, wd, acc[m][3]);
                }
            }
        }
        #pragma unroll
        for (int m = 0; m < 4; m++) {
            int n = ni * 4 + m;
            float bb = b1[n];
            #pragma unroll
            for (int j = 0; j < 4; j++) {
                float l = fmaxf(lo2(acc[m][j]) + bb, 0.f);
                float hgh = fmaxf(hi2(acc[m][j]) + bb, 0.f);
                sH_u[n * 16 + pi * 4 + j] = pack2(l, hgh);
            }
        }
    }
    __syncthreads();

    {   // GEMM2 + residual
        int ci = ni;
        ull acc[2][4];
        #pragma unroll
        for (int m = 0; m < 2; m++)
            #pragma unroll
            for (int j = 0; j < 4; j++) acc[m][j] = 0ull;
        const float4* w2v4 = (const float4*)w2;
        #pragma unroll 2
        for (int nt = 0; nt < 64; nt++) {
            float4 wv[2];
            wv[0] = w2v4[(ci * 2 + 0) * 64 + nt];
            wv[1] = w2v4[(ci * 2 + 1) * 64 + nt];
            ulonglong2 h2[4][2];
            #pragma unroll
            for (int kk = 0; kk < 4; kk++) {
                const ulonglong2* hp = (const ulonglong2*)(sH_u + (4 * nt + kk) * 16 + pi * 4);
                h2[kk][0] = hp[0]; h2[kk][1] = hp[1];
            }
            #pragma unroll
            for (int kk = 0; kk < 4; kk++) {
                #pragma unroll
                for (int m = 0; m < 2; m++) {
                    float wf = (kk == 0) ? wv[m].x : (kk == 1) ? wv[m].y : (kk == 2) ? wv[m].z : wv[m].w;
                    ull wd = dup2(wf);
                    fma2(acc[m][0], h2[kk][0].x, wd, acc[m][0]);
                    fma2(acc[m][1], h2[kk][0].y, wd, acc[m][1]);
                    fma2(acc[m][2], h2[kk][1].x, wd, acc[m][2]);
                    fma2(acc[m][3], h2[kk][1].y, wd, acc[m][3]);
                }
            }
        }
        #pragma unroll
        for (int m = 0; m < 2; m++) {
            int c = ci * 2 + m;
            ull bbd = dup2(b2[c]);
            float* og = out + (b * CC + c) * PP + (pix0 - b * PP) + pi * 8;
            #pragma unroll
            for (int j = 0; j < 4; j++) {
                ull ev = sE_u[c * 16 + pi * 4 + j];
                ull r;
                add2(r, acc[m][j], ev);
                add2(r, r, bbd);
                *(ull*)(og + 2 * j) = r;
            }
        }
    }
}

extern "C" void kernel_launch(void* const* d_in, const int* in_sizes, int n_in,
                              void* d_out, int out_size) {
    const float* x     = (const float*)d_in[0];
    const float* gamma = (const float*)d_in[1];
    const float* beta  = (const float*)d_in[2];
    const float* w1    = (const float*)d_in[3];
    const float* b1    = (const float*)d_in[4];
    const float* w2    = (const float*)d_in[5];
    const float* b2    = (const float*)d_in[6];
    float* out = (float*)d_out;

    dim3 gT(NT, 4, BB);
    k_t<<<gT, 256>>>(x);
    k_pix<<<BPP / 8, 256>>>();
    k_main<<<BPP / 8, 256>>>(gamma, beta);
    k_ffn<<<BPP / 32, 256>>>(w1, b1, w2, b2, out);
}